// round 1
// baseline (speedup 1.0000x reference)
#include <cuda_runtime.h>
#include <cuda_bf16.h>

#define IMG_W 416
#define IMG_H 416
#define NCH   3
#define MAXN  256
#define XQ    (IMG_W / 4)   // 104 float4 quads per row

// Per-sample theta coefficients: t00,t01,t02,t10,t11,t12 (padded to 8 for float4 loads)
__device__ float g_th[MAXN][8];
// Exact normalized coordinate table: (2i+1)/416 - 1 (W==H so one table serves both)
__device__ float g_xs[IMG_W];

__global__ void theta_kernel(const float* __restrict__ bb,
                             const float* __restrict__ angle,
                             const int* __restrict__ pos_ptr,
                             int N) {
    int n = threadIdx.x;

    // Fill exact coord table (matches reference's true division)
    if (n < IMG_W) {
        g_xs[n] = __fdiv_rn(2.0f * (float)n + 1.0f, (float)IMG_W) - 1.0f;
    }

    if (n >= N || n >= MAXN) return;

    // patch_ori_size may arrive as int32 or float32; handle both, default 300
    float patch_ori = 300.0f;
    if (pos_ptr) {
        int pi = pos_ptr[0];
        patch_ori = (pi > 0 && pi < 1000000) ? (float)pi : __int_as_float(pi);
    }

    float x1 = bb[n * 6 + 0];
    float y1 = bb[n * 6 + 1];
    float x2 = bb[n * 6 + 2];
    float y2 = bb[n * 6 + 3];

    float bwv = (x2 - x1) * (float)IMG_W;
    float bhv = (y2 - y1) * (float)IMG_H;
    float cx  = (x1 + x2) * 0.5f;
    float cy  = (y1 + y2) * 0.5f - (y2 - y1) * 0.1f;
    float tx  = (0.5f - cx) * 2.0f;
    float ty  = (0.5f - cy) * 2.0f;
    float target = 0.2f * sqrtf(bwv * bwv + bhv * bhv);
    float scale  = __fdiv_rn(target, patch_ori);

    float a = angle[n];
    float s = sinf(a);
    float c = cosf(a);

    g_th[n][0] = __fdiv_rn(c, scale);
    g_th[n][1] = __fdiv_rn(s, scale);
    g_th[n][2] = __fdiv_rn(tx * c + ty * s, scale);
    g_th[n][3] = __fdiv_rn(-s, scale);
    g_th[n][4] = __fdiv_rn(c, scale);
    g_th[n][5] = __fdiv_rn(-tx * s + ty * c, scale);
    g_th[n][6] = 0.0f;
    g_th[n][7] = 0.0f;
}

__global__ void __launch_bounds__(256)
sample_kernel(const float* __restrict__ img, float* __restrict__ out, int total) {
    int tid = blockIdx.x * blockDim.x + threadIdx.x;
    if (tid >= total) return;

    int xq = tid % XQ;
    int t2 = tid / XQ;
    int y  = t2 % IMG_H;
    int n  = t2 / IMG_H;

    const float4 th0 = *(const float4*)&g_th[n][0];   // t00 t01 t02 t10
    const float4 th1 = *(const float4*)&g_th[n][4];   // t11 t12 - -
    const float t00 = th0.x, t01 = th0.y, t02 = th0.z;
    const float t10 = th0.w, t11 = th1.x, t12 = th1.y;

    const float ysv = g_xs[y];
    const int xbase = xq * 4;

    float ixa[4], iya[4];
    bool any = false;
#pragma unroll
    for (int p = 0; p < 4; p++) {
        float xsv = g_xs[xbase + p];
        float gx = fmaf(t00, xsv, fmaf(t01, ysv, t02));
        float gy = fmaf(t10, xsv, fmaf(t11, ysv, t12));
        float ix = ((gx + 1.0f) * (float)IMG_W - 1.0f) * 0.5f;
        float iy = ((gy + 1.0f) * (float)IMG_H - 1.0f) * 0.5f;
        ixa[p] = ix;
        iya[p] = iy;
        any = any || (ix > -1.0f && ix < (float)IMG_W &&
                      iy > -1.0f && iy < (float)IMG_H);
    }

    const int cs    = IMG_H * IMG_W;
    const int obase = (n * NCH * IMG_H + y) * IMG_W + xbase;

    if (!any) {
        // Fast path (~99.7% of pixels): pure zero writes, no global reads.
        const float4 z = make_float4(0.f, 0.f, 0.f, 0.f);
        *(float4*)(out + obase)          = z;
        *(float4*)(out + obase + cs)     = z;
        *(float4*)(out + obase + 2 * cs) = z;
        return;
    }

    const float* base = img + n * NCH * cs;
    float acc0[4], acc1[4], acc2[4];
#pragma unroll
    for (int p = 0; p < 4; p++) {
        float ix = ixa[p], iy = iya[p];
        float fx0 = floorf(ix), fy0 = floorf(iy);
        int   x0  = (int)fx0,   y0  = (int)fy0;
        float wx1 = ix - fx0,   wy1 = iy - fy0;
        float wx0 = 1.0f - wx1, wy0 = 1.0f - wy1;

        bool vx0 = (x0 >= 0)  && (x0 < IMG_W);
        bool vx1 = (x0 >= -1) && (x0 < IMG_W - 1);
        bool vy0 = (y0 >= 0)  && (y0 < IMG_H);
        bool vy1 = (y0 >= -1) && (y0 < IMG_H - 1);

        float w00 = (vx0 && vy0) ? wx0 * wy0 : 0.0f;
        float w10 = (vx1 && vy0) ? wx1 * wy0 : 0.0f;
        float w01 = (vx0 && vy1) ? wx0 * wy1 : 0.0f;
        float w11 = (vx1 && vy1) ? wx1 * wy1 : 0.0f;

        float a0 = 0.f, a1 = 0.f, a2 = 0.f;
        int i00 = y0 * IMG_W + x0;
        if (w00 != 0.0f) {
            a0 = fmaf(w00, __ldg(base + i00), a0);
            a1 = fmaf(w00, __ldg(base + cs + i00), a1);
            a2 = fmaf(w00, __ldg(base + 2 * cs + i00), a2);
        }
        if (w10 != 0.0f) {
            int i = i00 + 1;
            a0 = fmaf(w10, __ldg(base + i), a0);
            a1 = fmaf(w10, __ldg(base + cs + i), a1);
            a2 = fmaf(w10, __ldg(base + 2 * cs + i), a2);
        }
        if (w01 != 0.0f) {
            int i = i00 + IMG_W;
            a0 = fmaf(w01, __ldg(base + i), a0);
            a1 = fmaf(w01, __ldg(base + cs + i), a1);
            a2 = fmaf(w01, __ldg(base + 2 * cs + i), a2);
        }
        if (w11 != 0.0f) {
            int i = i00 + IMG_W + 1;
            a0 = fmaf(w11, __ldg(base + i), a0);
            a1 = fmaf(w11, __ldg(base + cs + i), a1);
            a2 = fmaf(w11, __ldg(base + 2 * cs + i), a2);
        }
        acc0[p] = a0;
        acc1[p] = a1;
        acc2[p] = a2;
    }

    *(float4*)(out + obase)          = make_float4(acc0[0], acc0[1], acc0[2], acc0[3]);
    *(float4*)(out + obase + cs)     = make_float4(acc1[0], acc1[1], acc1[2], acc1[3]);
    *(float4*)(out + obase + 2 * cs) = make_float4(acc2[0], acc2[1], acc2[2], acc2[3]);
}

extern "C" void kernel_launch(void* const* d_in, const int* in_sizes, int n_in,
                              void* d_out, int out_size) {
    const float* img = (const float*)d_in[0];   // adv_patch_batch (B,L,C,H,W) f32
    const float* bb  = (const float*)d_in[1];   // bboxes_batch (B,L,6) f32
    const float* ang = (const float*)d_in[2];   // angle (B*L,) f32
    const int*   pos = (n_in > 3) ? (const int*)d_in[3] : nullptr;  // patch_ori_size

    int N = in_sizes[2];                        // B*L = 128
    if (N > MAXN) N = MAXN;

    theta_kernel<<<1, 512>>>(bb, ang, pos, N);

    int total = N * IMG_H * XQ;
    sample_kernel<<<(total + 255) / 256, 256>>>(img, (float*)d_out, total);
}